// round 13
// baseline (speedup 1.0000x reference)
#include <cuda_runtime.h>
#include <cuda_bf16.h>
#include <stdint.h>
#include <math.h>

#define NEG_INF (-1e9f)

#define Bsz 32
#define LQ  1024
#define LK  1024
#define DIM 1024

typedef __nv_bfloat16  bf16;
typedef __nv_bfloat162 bf162;

// ---------------------------------------------------------------------------
// Scratch (__device__ globals; allocation-free rule).
// ---------------------------------------------------------------------------
__device__ bf16 g_combh[(long long)Bsz * LQ * 2 * DIM];  // [32768,2048] mix|q
__device__ bf16 g_combl[(long long)Bsz * LQ * 2 * DIM];  // q half only used
__device__ bf16 g_wh[(long long)Bsz * LQ * LK];          // softmax weights hi
__device__ bf16 g_qryh[(long long)Bsz * LQ * DIM];
__device__ bf16 g_qryl[(long long)Bsz * LQ * DIM];
__device__ bf16 g_ctxh[(long long)Bsz * LK * DIM];
__device__ bf16 g_ctxl[(long long)Bsz * LK * DIM];
__device__ bf16 g_ctxTh[(long long)Bsz * DIM * LK];
__device__ bf16 g_winh[DIM * DIM];
__device__ bf16 g_winl[DIM * DIM];
__device__ bf16 g_wouth[DIM * 2 * DIM];
__device__ float g_meanf[Bsz * DIM];
__device__ bf16  g_mdh[Bsz * DIM];
__device__ float g_biasd[Bsz * DIM];
// fp8 (e5m2) replicas for cross-correction MMAs (K4/K5)
__device__ uint8_t g_w8h[(long long)Bsz * LQ * LK];      // e5m2(w)
__device__ uint8_t g_w8l[(long long)Bsz * LQ * LK];      // e5m2(w_lo)
__device__ uint8_t g_ctxT8h[(long long)Bsz * DIM * LK];  // e5m2(ctxT)
__device__ uint8_t g_ctxT8l[(long long)Bsz * DIM * LK];  // e5m2(ctxT_lo)
__device__ uint8_t g_comb8h[(long long)Bsz * LQ * 2 * DIM]; // e5m2(comb*2^-4)
__device__ uint8_t g_comb8l[(long long)Bsz * LQ * 2 * DIM]; // e5m2(comb_lo)
__device__ uint8_t g_wout8h[DIM * 2 * DIM];              // e5m2(Wout)
__device__ uint8_t g_wout8l[DIM * 2 * DIM];              // e5m2(Wout_lo*2^4)
__device__ uint8_t g_md8h[Bsz * DIM];                    // e5m2(mean*2^-4)
__device__ uint8_t g_md8l[Bsz * DIM];                    // e5m2(mean_lo)

// ---------------------------------------------------------------------------
#define SW128(off) ((off) ^ (((off) >> 3) & 0x70))

__device__ __forceinline__ uint32_t smem_u32(const void* p) {
    uint32_t a;
    asm("{ .reg .u64 t; cvta.to.shared.u64 t, %1; cvt.u32.u64 %0, t; }"
        : "=r"(a) : "l"(p));
    return a;
}
__device__ __forceinline__ void cp16(uint32_t dst, const void* src) {
    asm volatile("cp.async.cg.shared.global [%0], [%1], 16;"
                 :: "r"(dst), "l"(src) : "memory");
}
#define CP_COMMIT() asm volatile("cp.async.commit_group;" ::: "memory")
#define CP_WAIT1()  asm volatile("cp.async.wait_group 1;" ::: "memory")

__device__ __forceinline__ void ldsm4(uint32_t* r, uint32_t addr) {
    asm volatile("ldmatrix.sync.aligned.m8n8.x4.shared.b16 {%0,%1,%2,%3}, [%4];"
                 : "=r"(r[0]), "=r"(r[1]), "=r"(r[2]), "=r"(r[3]) : "r"(addr));
}
__device__ __forceinline__ void mma16816(float* c, const uint32_t* a,
                                         uint32_t b0, uint32_t b1) {
    asm volatile(
        "mma.sync.aligned.m16n8k16.row.col.f32.bf16.bf16.f32 "
        "{%0,%1,%2,%3}, {%4,%5,%6,%7}, {%8,%9}, {%0,%1,%2,%3};"
        : "+f"(c[0]), "+f"(c[1]), "+f"(c[2]), "+f"(c[3])
        : "r"(a[0]), "r"(a[1]), "r"(a[2]), "r"(a[3]), "r"(b0), "r"(b1));
}
// fp8 e5m2 k32 MMA: same fragment register counts as bf16 k16
__device__ __forceinline__ void mma16832(float* c, const uint32_t* a,
                                         uint32_t b0, uint32_t b1) {
    asm volatile(
        "mma.sync.aligned.m16n8k32.row.col.f32.e5m2.e5m2.f32 "
        "{%0,%1,%2,%3}, {%4,%5,%6,%7}, {%8,%9}, {%0,%1,%2,%3};"
        : "+f"(c[0]), "+f"(c[1]), "+f"(c[2]), "+f"(c[3])
        : "r"(a[0]), "r"(a[1]), "r"(a[2]), "r"(a[3]), "r"(b0), "r"(b1));
}

__device__ __forceinline__ void split2(float a, float b, bf162& hi, bf162& lo) {
    hi = __floats2bfloat162_rn(a, b);
    float2 hf = __bfloat1622float2(hi);
    lo = __floats2bfloat162_rn(a - hf.x, b - hf.y);
}
// pack two floats to e5m2x2: low byte = v0 (element k), high byte = v1 (k+1)
__device__ __forceinline__ uint16_t cvt_e5m2x2(float v0, float v1) {
    uint16_t r;
    asm("cvt.rn.satfinite.e5m2x2.f32 %0, %1, %2;" : "=h"(r) : "f"(v1), "f"(v0));
    return r;
}

// ---------------------------------------------------------------------------
// Tile geometry: CTA 256x128, K-chunk 64, 512 threads, 2-stage cp.async.
// FP8=1: ALO slot holds A8 = [hiA8|loA8] (128B rows), BLO slot holds
//        B8 = [loB8|hiB8]; cross terms via e5m2 k32 MMAs.
// ---------------------------------------------------------------------------
#define TM 256
#define TN 128
#define KC 64
#define NTHR 512
#define OFF_AHI   0
#define OFF_ALO   32768
#define OFF_BHI   65536
#define OFF_BLO   81920
#define STAGE     98304
#define SM_TOTAL  (2 * STAGE)   // 196608

// EPI: 0 split out (bf16 hi + fp8 replicas), 1 mask fp32, 2 tanh fp32
// TRUNC: 0 none | 1 K4 semantics | 2 K5 semantics
// FP8: cross terms in e5m2 (K4/K5) vs bf16 split-3 (K1/K2)
template <int EPI, int TRUNC, int FP8>
__global__ __launch_bounds__(NTHR, 1)
void mma_gemm(const bf16* __restrict__ Ahi, const bf16* __restrict__ Alo,
              const uint8_t* __restrict__ A8h, const uint8_t* __restrict__ A8l,
              const bf16* __restrict__ Bhi, const bf16* __restrict__ Blo,
              const uint8_t* __restrict__ B8lo, const uint8_t* __restrict__ B8hi,
              float* __restrict__ Cf, bf16* __restrict__ Chi, bf16* __restrict__ Clo,
              uint8_t* __restrict__ C8h, uint8_t* __restrict__ C8l,
              int K, int lda, int ldb, int ldc,
              long long sA, long long sB, long long sC,
              const int* __restrict__ ql, const int* __restrict__ cl,
              const bf16* __restrict__ Dh,
              const uint8_t* __restrict__ D8h, const uint8_t* __restrict__ D8l,
              const float* __restrict__ bias)
{
    extern __shared__ char smem[];
    const uint32_t sb = smem_u32(smem);
    const int tid  = threadIdx.x;
    const int wid  = tid >> 5;
    const int lane = tid & 31;
    const int bz = blockIdx.z;
    const int m0 = blockIdx.y * TM;
    const int n0 = blockIdx.x * TN;

    int qlen = 0, clen = 0;

    if (EPI == 1) {
        qlen = ql[bz]; clen = cl[bz];
        if (m0 >= qlen || n0 >= clen) {
            const float4 ninf = make_float4(NEG_INF, NEG_INF, NEG_INF, NEG_INF);
            float* base = Cf + (long long)bz * sC;
#pragma unroll 4
            for (int i = tid; i < TM * (TN / 4); i += NTHR) {
                const int r = i / (TN / 4);
                const int c = (i % (TN / 4)) * 4;
                *(float4*)(base + (long long)(m0 + r) * ldc + n0 + c) = ninf;
            }
            return;
        }
    }

    int S = K / KC;

    if (TRUNC == 1) {
        qlen = ql[bz]; clen = cl[bz];
        if (m0 >= qlen) {   // dead tile: broadcast per-batch context mean
            for (int i = tid; i < TM * (TN / 2); i += NTHR) {
                const int r  = i / (TN / 2);
                const int c2 = (i % (TN / 2)) * 2;
                const long long o = (long long)bz * sC + (long long)(m0 + r) * ldc + n0 + c2;
                *(bf162*)(Chi + o)    = *(const bf162*)(Dh + bz * DIM + n0 + c2);
                *(uint16_t*)(C8h + o) = *(const uint16_t*)(D8h + bz * DIM + n0 + c2);
                *(uint16_t*)(C8l + o) = *(const uint16_t*)(D8l + bz * DIM + n0 + c2);
            }
            return;
        }
        const int se = (clen + KC - 1) / KC;
        if (se < S) S = se;
    }

    bool dead5 = false;
    int batch5 = 0;
    if (TRUNC == 2) {
        batch5 = m0 >> 10;
        qlen = ql[batch5];
        if ((m0 & (LQ - 1)) >= qlen) { dead5 = true; S = S / 2; }
    }
    const int koff = dead5 ? (K / 2) : 0;

    // A fill: 256 rows, 2 threads/row
    const int arow = tid >> 1;
    const bf16* Ah = Ahi + (long long)bz * sA + (long long)(m0 + arow) * lda + koff + (tid & 1) * 32;
    const bf16* Al = nullptr;
    const uint8_t* A8p = nullptr;
    if (FP8) {
        const uint8_t* as = (tid & 1) ? A8l : A8h;
        A8p = as + (long long)bz * sA + (long long)(m0 + arow) * lda + koff;
    } else {
        Al = Alo + (long long)bz * sA + (long long)(m0 + arow) * lda + koff + (tid & 1) * 32;
    }
    const uint32_t fbA = (uint32_t)(arow * 128 + (tid & 1) * 64);
    // B fill: 128 rows, 4 threads/row
    const int brow = tid >> 2;
    const bf16* Bh = Bhi + (long long)bz * sB + (long long)(n0 + brow) * ldb + koff + (tid & 3) * 16;
    const bf16* Bl = nullptr;
    const uint8_t* B8p = nullptr;
    if (FP8) {
        const uint8_t* bs = ((tid & 3) < 2) ? B8lo : B8hi;
        B8p = bs + (long long)bz * sB + (long long)(n0 + brow) * ldb + koff + ((tid & 3) & 1) * 32;
    } else {
        Bl = Blo + (long long)bz * sB + (long long)(n0 + brow) * ldb + koff + (tid & 3) * 16;
    }
    const uint32_t fbB = (uint32_t)(brow * 128 + (tid & 3) * 32);

    auto issue = [&](int s) {
        const uint32_t st = sb + (s & 1) * STAGE;
        const int k0 = s * KC;
#pragma unroll
        for (int j = 0; j < 4; j++) {
            const uint32_t sw = SW128(fbA + j * 16);
            cp16(st + OFF_AHI + sw, Ah + k0 + j * 8);
            if (FP8) cp16(st + OFF_ALO + sw, A8p + k0 + j * 16);
            else     cp16(st + OFF_ALO + sw, Al + k0 + j * 8);
        }
#pragma unroll
        for (int j = 0; j < 2; j++) {
            const uint32_t sw = SW128(fbB + j * 16);
            cp16(st + OFF_BHI + sw, Bh + k0 + j * 8);
            if (FP8) cp16(st + OFF_BLO + sw, B8p + k0 + j * 16);
            else     cp16(st + OFF_BLO + sw, Bl + k0 + j * 8);
        }
        CP_COMMIT();
    };

    issue(0);
    if (S > 1) issue(1); else CP_COMMIT();

    const int wm = (wid & 3) * 64;
    const int wn = (wid >> 2) * 32;
    const int lrow8 = (lane & 7) + ((lane >> 3) & 1) * 8;
    const int lk16  = ((lane >> 4) & 1) * 16;

    float acc[4][4][4];
#pragma unroll
    for (int mt = 0; mt < 4; mt++)
#pragma unroll
        for (int nt = 0; nt < 4; nt++)
#pragma unroll
            for (int i = 0; i < 4; i++) acc[mt][nt][i] = 0.f;

    for (int s = 0; s < S; s++) {
        CP_WAIT1();
        __syncthreads();

        const uint32_t st = sb + (s & 1) * STAGE;
#pragma unroll
        for (int ks = 0; ks < KC / 16; ks++) {
            uint32_t bhi[2][4], bx[2][4];
#pragma unroll
            for (int bt = 0; bt < 2; bt++) {
                uint32_t off = SW128((uint32_t)((wn + bt * 16 + lrow8) * 128 + ks * 32 + lk16));
                ldsm4(bhi[bt], st + OFF_BHI + off);
                ldsm4(bx[bt],  st + OFF_BLO + off);
            }
#pragma unroll
            for (int mt = 0; mt < 4; mt++) {
                uint32_t ahi[4], ax[4];
                uint32_t off = SW128((uint32_t)((wm + mt * 16 + lrow8) * 128 + ks * 32 + lk16));
                ldsm4(ahi, st + OFF_AHI + off);
                ldsm4(ax,  st + OFF_ALO + off);
#pragma unroll
                for (int nt = 0; nt < 4; nt++)
                    mma16816(acc[mt][nt], ahi, bhi[nt >> 1][nt & 1], bhi[nt >> 1][(nt & 1) + 2]);
                if (FP8) {
                    // e5m2 k32: covers hiA*loB (ks 0,1) and loA*hiB (ks 2,3)
#pragma unroll
                    for (int nt = 0; nt < 4; nt++)
                        mma16832(acc[mt][nt], ax, bx[nt >> 1][nt & 1], bx[nt >> 1][(nt & 1) + 2]);
                } else {
#pragma unroll
                    for (int nt = 0; nt < 4; nt++)
                        mma16816(acc[mt][nt], ahi, bx[nt >> 1][nt & 1], bx[nt >> 1][(nt & 1) + 2]);
#pragma unroll
                    for (int nt = 0; nt < 4; nt++)
                        mma16816(acc[mt][nt], ax, bhi[nt >> 1][nt & 1], bhi[nt >> 1][(nt & 1) + 2]);
                }
            }
        }
        __syncthreads();
        if (s + 2 < S) issue(s + 2);
    }

    // ------------------------- epilogue -------------------------
    const int rq = lane >> 2;
    const int cq = (lane & 3) * 2;

#pragma unroll
    for (int mt = 0; mt < 4; mt++) {
#pragma unroll
        for (int half = 0; half < 2; half++) {
            const int gm = m0 + wm + mt * 16 + rq + half * 8;
            const bool rowdead = (EPI == 1 || TRUNC == 1) && (gm >= qlen);
#pragma unroll
            for (int nt = 0; nt < 4; nt++) {
                const int gn = n0 + wn + nt * 8 + cq;
                float v0 = acc[mt][nt][half * 2 + 0];
                float v1 = acc[mt][nt][half * 2 + 1];
                const long long o = (long long)bz * sC + (long long)gm * ldc + gn;
                if (EPI == 0) {
                    if (TRUNC == 1 && rowdead) {
                        *(bf162*)(Chi + o)    = *(const bf162*)(Dh + bz * DIM + gn);
                        *(uint16_t*)(C8h + o) = *(const uint16_t*)(D8h + bz * DIM + gn);
                        *(uint16_t*)(C8l + o) = *(const uint16_t*)(D8l + bz * DIM + gn);
                    } else {
                        bf162 hp, lp;
                        split2(v0, v1, hp, lp);
                        *(bf162*)(Chi + o) = hp;
                        if (!FP8) *(bf162*)(Clo + o) = lp;
                        float2 lf = __bfloat1622float2(lp);
                        *(uint16_t*)(C8h + o) = cvt_e5m2x2(v0 * 0.0625f, v1 * 0.0625f);
                        *(uint16_t*)(C8l + o) = cvt_e5m2x2(lf.x, lf.y);
                    }
                } else {
                    if (EPI == 1) {
                        if (rowdead || gn     >= clen) v0 = NEG_INF;
                        if (rowdead || gn + 1 >= clen) v1 = NEG_INF;
                    }
                    if (EPI == 2) {
                        if (TRUNC == 2 && dead5) {
                            v0 += bias[batch5 * DIM + gn];
                            v1 += bias[batch5 * DIM + gn + 1];
                        }
                        v0 = tanhf(v0); v1 = tanhf(v1);
                    }
                    *(float2*)(Cf + o) = make_float2(v0, v1);
                }
            }
        }
    }
}

// ---------------------------------------------------------------------------
// fp32 -> (hi, lo) bf16 split (query, W_in)
// ---------------------------------------------------------------------------
__global__ __launch_bounds__(256)
void convert_split(const float4* __restrict__ src, bf162* __restrict__ hi,
                   bf162* __restrict__ lo, long long n4)
{
    const long long i = (long long)blockIdx.x * blockDim.x + threadIdx.x;
    if (i >= n4) return;
    float4 v = src[i];
    bf162 h0, l0, h1, l1;
    split2(v.x, v.y, h0, l0);
    split2(v.z, v.w, h1, l1);
    hi[2 * i] = h0; hi[2 * i + 1] = h1;
    lo[2 * i] = l0; lo[2 * i + 1] = l1;
}

// ---------------------------------------------------------------------------
// W_out: bf16 hi + fp8 replicas (hi at scale 1, lo at scale 2^4)
// ---------------------------------------------------------------------------
__global__ __launch_bounds__(256)
void convert_wout(const float4* __restrict__ src, bf162* __restrict__ hi,
                  uint16_t* __restrict__ f8h, uint16_t* __restrict__ f8l,
                  long long n4)
{
    const long long i = (long long)blockIdx.x * blockDim.x + threadIdx.x;
    if (i >= n4) return;
    float4 v = src[i];
    bf162 h0, l0, h1, l1;
    split2(v.x, v.y, h0, l0);
    split2(v.z, v.w, h1, l1);
    hi[2 * i] = h0; hi[2 * i + 1] = h1;
    float2 la = __bfloat1622float2(l0), lb = __bfloat1622float2(l1);
    f8h[2 * i]     = cvt_e5m2x2(v.x, v.y);
    f8h[2 * i + 1] = cvt_e5m2x2(v.z, v.w);
    f8l[2 * i]     = cvt_e5m2x2(la.x * 16.0f, la.y * 16.0f);
    f8l[2 * i + 1] = cvt_e5m2x2(lb.x * 16.0f, lb.y * 16.0f);
}

// ---------------------------------------------------------------------------
// context: bf16 hi/lo (for K2) + transposed bf16 hi + fp8 hi/lo (for K4)
// ---------------------------------------------------------------------------
__global__ __launch_bounds__(256)
void transpose_convert(const float* __restrict__ src,
                       bf16* __restrict__ ch, bf16* __restrict__ cl_,
                       bf16* __restrict__ th,
                       uint8_t* __restrict__ t8h, uint8_t* __restrict__ t8l)
{
    __shared__ float t[32][33];
    const long long bo = (long long)blockIdx.z * LK * DIM;
    const int x = blockIdx.x * 32 + threadIdx.x;
    const int y = blockIdx.y * 32 + threadIdx.y;
#pragma unroll
    for (int i = 0; i < 32; i += 8) {
        float v = src[bo + (long long)(y + i) * DIM + x];
        t[threadIdx.y + i][threadIdx.x] = v;
        bf16 h = __float2bfloat16_rn(v);
        ch[bo + (long long)(y + i) * DIM + x] = h;
        cl_[bo + (long long)(y + i) * DIM + x] =
            __float2bfloat16_rn(v - __bfloat162float(h));
    }
    __syncthreads();
    const int x2 = blockIdx.y * 32 + threadIdx.x;
    const int y2 = blockIdx.x * 32 + threadIdx.y;
#pragma unroll
    for (int i = 0; i < 32; i += 8) {
        float v = t[threadIdx.x][threadIdx.y + i];
        bf16 h = __float2bfloat16_rn(v);
        float lo = v - __bfloat162float(h);
        const long long o = bo + (long long)(y2 + i) * LK + x2;
        th[o] = h;
        t8h[o] = (uint8_t)cvt_e5m2x2(v, 0.f);
        t8l[o] = (uint8_t)cvt_e5m2x2(lo, 0.f);
    }
}

// ---------------------------------------------------------------------------
// per-batch context mean (fp32 + bf16 hi + fp8 replicas)
// ---------------------------------------------------------------------------
__global__ __launch_bounds__(256)
void ctx_mean(const float* __restrict__ ctx, float* __restrict__ meanf,
              bf16* __restrict__ mh,
              uint8_t* __restrict__ m8h, uint8_t* __restrict__ m8l)
{
    const int b = blockIdx.y;
    const int d = blockIdx.x * 256 + threadIdx.x;
    const float* p = ctx + (long long)b * LK * DIM + d;
    float s = 0.f;
#pragma unroll 8
    for (int k = 0; k < LK; k++) s += p[(long long)k * DIM];
    s *= (1.0f / (float)LK);
    meanf[b * DIM + d] = s;
    bf16 h = __float2bfloat16_rn(s);
    mh[b * DIM + d] = h;
    float lo = s - __bfloat162float(h);
    m8h[b * DIM + d] = (uint8_t)cvt_e5m2x2(s * 0.0625f, 0.f);
    m8l[b * DIM + d] = (uint8_t)cvt_e5m2x2(lo, 0.f);
}

// ---------------------------------------------------------------------------
// bias[b][d] = mean[b] . Wout_mix[d]  (fp32, warp per output)
// ---------------------------------------------------------------------------
__global__ __launch_bounds__(256)
void bias_gemm(const float* __restrict__ meanf, const float* __restrict__ Wout,
               float* __restrict__ bias)
{
    const int gw = (blockIdx.x * 256 + threadIdx.x) >> 5;
    const int lane = threadIdx.x & 31;
    if (gw >= Bsz * DIM) return;
    const int b = gw >> 10, d = gw & (DIM - 1);
    const float* m = meanf + b * DIM;
    const float* w = Wout + (long long)d * (2 * DIM);
    float s = 0.f;
#pragma unroll 4
    for (int c = lane; c < DIM; c += 32) s += m[c] * w[c];
#pragma unroll
    for (int o = 16; o > 0; o >>= 1) s += __shfl_xor_sync(0xffffffffu, s, o);
    if (lane == 0) bias[gw] = s;
}

// ---------------------------------------------------------------------------
// Row softmax; emits bf16 hi + fp8 hi/lo weights. Dead rows: exact 1/1024.
// ---------------------------------------------------------------------------
__global__ __launch_bounds__(256)
void softmax_kernel(const float* __restrict__ scores,
                    bf16* __restrict__ wh,
                    uint8_t* __restrict__ w8h, uint8_t* __restrict__ w8l,
                    const int* __restrict__ ql)
{
    const long long row = blockIdx.x;
    const int t = threadIdx.x;
    const int b = (int)(row >> 10);
    const int r = (int)(row & (LQ - 1));

    if (r >= ql[b]) {
        const float u = 1.0f / 1024.0f;            // 2^-10: exact in bf16/e5m2
        const bf162 h = __floats2bfloat162_rn(u, u);
        const uint16_t u8 = cvt_e5m2x2(u, u);
        *(bf162*)(wh + row * LK + 2 * t) = h;
        *(bf162*)(wh + row * LK + 2 * t + 512) = h;
        *(uint16_t*)(w8h + row * LK + 2 * t) = u8;
        *(uint16_t*)(w8h + row * LK + 2 * t + 512) = u8;
        *(uint16_t*)(w8l + row * LK + 2 * t) = 0;
        *(uint16_t*)(w8l + row * LK + 2 * t + 512) = 0;
        return;
    }

    const float* s = scores + row * LK;
    float2 x0 = *(const float2*)(s + 2 * t);
    float2 x1 = *(const float2*)(s + 2 * t + 512);
    float lmax = fmaxf(fmaxf(x0.x, x0.y), fmaxf(x1.x, x1.y));

    __shared__ float red[8];
#pragma unroll
    for (int o = 16; o > 0; o >>= 1) lmax = fmaxf(lmax, __shfl_xor_sync(0xffffffffu, lmax, o));
    if ((t & 31) == 0) red[t >> 5] = lmax;
    __syncthreads();
    if (t < 32) {
        float m = (t < 8) ? red[t] : -INFINITY;
#pragma unroll
        for (int o = 4; o > 0; o >>= 1) m = fmaxf(m, __shfl_xor_sync(0xffffffffu, m, o));
        if (t == 0) red[0] = m;
    }
    __syncthreads();
    const float m = red[0];

    float e0 = __expf(x0.x - m), e1 = __expf(x0.y - m);
    float e2 = __expf(x1.x - m), e3 = __expf(x1.y - m);
    float lsum = e0 + e1 + e2 + e3;
#pragma unroll
    for (int o = 16; o > 0; o >>= 1) lsum += __shfl_xor_sync(0xffffffffu, lsum, o);
    __shared__ float red2[8];
    if ((t & 31) == 0) red2[t >> 5] = lsum;
    __syncthreads();
    if (t < 32) {
        float x = (t < 8) ? red2[t] : 0.f;
#pragma unroll
        for (int o = 4; o > 0; o >>= 1) x += __shfl_xor_sync(0xffffffffu, x, o);
        if (t == 0) red2[0] = x;
    }
    __syncthreads();
    const float inv = 1.0f / red2[0];

    float w0 = e0 * inv, w1 = e1 * inv, w2 = e2 * inv, w3 = e3 * inv;
    bf162 h, l;
    split2(w0, w1, h, l);
    *(bf162*)(wh + row * LK + 2 * t) = h;
    float2 lf = __bfloat1622float2(l);
    *(uint16_t*)(w8h + row * LK + 2 * t) = cvt_e5m2x2(w0, w1);
    *(uint16_t*)(w8l + row * LK + 2 * t) = cvt_e5m2x2(lf.x, lf.y);
    split2(w2, w3, h, l);
    *(bf162*)(wh + row * LK + 2 * t + 512) = h;
    lf = __bfloat1622float2(l);
    *(uint16_t*)(w8h + row * LK + 2 * t + 512) = cvt_e5m2x2(w2, w3);
    *(uint16_t*)(w8l + row * LK + 2 * t + 512) = cvt_e5m2x2(lf.x, lf.y);
}

// ---------------------------------------------------------------------------
extern "C" void kernel_launch(void* const* d_in, const int* in_sizes, int n_in,
                              void* d_out, int out_size)
{
    const float* query   = (const float*)d_in[0];
    const float* context = (const float*)d_in[1];
    const int*   ql      = (const int*)d_in[2];
    const int*   cl      = (const int*)d_in[3];
    const float* W_in    = (const float*)d_in[4];
    const float* W_out   = (const float*)d_in[5];

    float* out        = (float*)d_out;
    float* scores_out = out + (long long)Bsz * LQ * DIM;

    bf16 *combh, *combl, *wh, *qryh, *qryl, *ctxh, *ctxl, *ctxTh;
    bf16 *winh, *winl, *wouth, *mdh;
    uint8_t *w8h, *w8l, *ctxT8h, *ctxT8l, *comb8h, *comb8l, *wout8h, *wout8l, *md8h, *md8l;
    float *meanf, *biasd;
    cudaGetSymbolAddress((void**)&combh,  g_combh);
    cudaGetSymbolAddress((void**)&combl,  g_combl);
    cudaGetSymbolAddress((void**)&wh,     g_wh);
    cudaGetSymbolAddress((void**)&qryh,   g_qryh);
    cudaGetSymbolAddress((void**)&qryl,   g_qryl);
    cudaGetSymbolAddress((void**)&ctxh,   g_ctxh);
    cudaGetSymbolAddress((void**)&ctxl,   g_ctxl);
    cudaGetSymbolAddress((void**)&ctxTh,  g_ctxTh);
    cudaGetSymbolAddress((void**)&winh,   g_winh);
    cudaGetSymbolAddress((void**)&winl,   g_winl);
    cudaGetSymbolAddress((void**)&wouth,  g_wouth);
    cudaGetSymbolAddress((void**)&mdh,    g_mdh);
    cudaGetSymbolAddress((void**)&w8h,    g_w8h);
    cudaGetSymbolAddress((void**)&w8l,    g_w8l);
    cudaGetSymbolAddress((void**)&ctxT8h, g_ctxT8h);
    cudaGetSymbolAddress((void**)&ctxT8l, g_ctxT8l);
    cudaGetSymbolAddress((void**)&comb8h, g_comb8h);
    cudaGetSymbolAddress((void**)&comb8l, g_comb8l);
    cudaGetSymbolAddress((void**)&wout8h, g_wout8h);
    cudaGetSymbolAddress((void**)&wout8l, g_wout8l);
    cudaGetSymbolAddress((void**)&md8h,   g_md8h);
    cudaGetSymbolAddress((void**)&md8l,   g_md8l);
    cudaGetSymbolAddress((void**)&meanf,  g_meanf);
    cudaGetSymbolAddress((void**)&biasd,  g_biasd);

    cudaFuncSetAttribute(mma_gemm<0, 0, 0>, cudaFuncAttributeMaxDynamicSharedMemorySize, SM_TOTAL);
    cudaFuncSetAttribute(mma_gemm<1, 0, 0>, cudaFuncAttributeMaxDynamicSharedMemorySize, SM_TOTAL);
    cudaFuncSetAttribute(mma_gemm<0, 1, 1>, cudaFuncAttributeMaxDynamicSharedMemorySize, SM_TOTAL);
    cudaFuncSetAttribute(mma_gemm<2, 2, 1>, cudaFuncAttributeMaxDynamicSharedMemorySize, SM_TOTAL);

    const long long M_all = (long long)Bsz * LQ;

    static cudaStream_t s1 = nullptr, s2 = nullptr;
    static cudaEvent_t  ef = nullptr, e1 = nullptr, e2 = nullptr;
    if (s1 == nullptr) {
        cudaStreamCreateWithFlags(&s1, cudaStreamNonBlocking);
        cudaStreamCreateWithFlags(&s2, cudaStreamNonBlocking);
        cudaEventCreateWithFlags(&ef, cudaEventDisableTiming);
        cudaEventCreateWithFlags(&e1, cudaEventDisableTiming);
        cudaEventCreateWithFlags(&e2, cudaEventDisableTiming);
    }

    cudaEventRecord(ef, 0);
    cudaStreamWaitEvent(s1, ef, 0);
    cudaStreamWaitEvent(s2, ef, 0);

    // branch s1: context transforms -> mean -> dead-row bias
    transpose_convert<<<dim3(32, 32, Bsz), dim3(32, 8), 0, s1>>>(
        context, ctxh, ctxl, ctxTh, ctxT8h, ctxT8l);
    ctx_mean<<<dim3(DIM / 256, Bsz), 256, 0, s1>>>(context, meanf, mdh, md8h, md8l);
    bias_gemm<<<(Bsz * DIM * 32) / 256, 256, 0, s1>>>(meanf, W_out, biasd);
    cudaEventRecord(e1, s1);

    // branch s2: W_out conversion (bf16 hi + fp8 hi/lo)
    {
        long long o4 = (long long)DIM * 2 * DIM / 4;
        convert_wout<<<(unsigned)((o4 + 255) / 256), 256, 0, s2>>>(
            (const float4*)W_out, (bf162*)wouth, (uint16_t*)wout8h, (uint16_t*)wout8l, o4);
        cudaEventRecord(e2, s2);
    }

    // main branch: query/W_in conversion then K1
    {
        long long n4 = (long long)Bsz * LQ * DIM / 4;
        convert_split<<<(unsigned)((n4 + 255) / 256), 256>>>(
            (const float4*)query, (bf162*)qryh, (bf162*)qryl, n4);
        long long w4 = (long long)DIM * DIM / 4;
        convert_split<<<(unsigned)((w4 + 255) / 256), 256>>>(
            (const float4*)W_in, (bf162*)winh, (bf162*)winl, w4);
    }

    // K1: q = query @ W_in^T -> comb q half (bf16 hi/lo + fp8 replicas)
    mma_gemm<0, 0, 0><<<dim3(DIM / TN, (unsigned)(M_all / TM), 1), NTHR, SM_TOTAL>>>(
        qryh, qryl, nullptr, nullptr, winh, winl, nullptr, nullptr,
        nullptr, combh + DIM, combl + DIM, comb8h + DIM, comb8l + DIM,
        DIM, DIM, DIM, 2 * DIM, 0, 0, 0, nullptr, nullptr,
        nullptr, nullptr, nullptr, nullptr);

    cudaStreamWaitEvent(0, e1, 0);
    cudaStreamWaitEvent(0, e2, 0);

    // K2: scores (bf16 split-3, masked fp32 out; dead tiles fill)
    mma_gemm<1, 0, 0><<<dim3(LK / TN, LQ / TM, Bsz), NTHR, SM_TOTAL>>>(
        combh + DIM, combl + DIM, nullptr, nullptr, ctxh, ctxl, nullptr, nullptr,
        scores_out, nullptr, nullptr, nullptr, nullptr,
        DIM, 2 * DIM, DIM, LK,
        (long long)LQ * 2 * DIM, (long long)LK * DIM, (long long)LQ * LK, ql, cl,
        nullptr, nullptr, nullptr, nullptr);

    // K3: softmax -> bf16 hi + fp8 weights
    softmax_kernel<<<(unsigned)M_all, 256>>>(scores_out, wh, w8h, w8l, ql);

    // K4: mix (fp8 cross terms), dead tiles mean fill, K-trunc at cl
    mma_gemm<0, 1, 1><<<dim3(DIM / TN, LQ / TM, Bsz), NTHR, SM_TOTAL>>>(
        wh, nullptr, w8h, w8l, ctxTh, nullptr, ctxT8l, ctxT8h,
        nullptr, combh, nullptr, comb8h, comb8l,
        LK, LK, LK, 2 * DIM,
        (long long)LQ * LK, (long long)DIM * LK, (long long)LQ * 2 * DIM, ql, cl,
        mdh, md8h, md8l, nullptr);

    // K5: out = tanh(comb @ W_out^T) (fp8 cross terms; dead rows q-half+bias)
    mma_gemm<2, 2, 1><<<dim3(DIM / TN, (unsigned)(M_all / TM), 1), NTHR, SM_TOTAL>>>(
        combh, nullptr, comb8h, comb8l, wouth, nullptr, wout8l, wout8h,
        out, nullptr, nullptr, nullptr, nullptr,
        2 * DIM, 2 * DIM, 2 * DIM, DIM, 0, 0, 0, ql, nullptr,
        nullptr, nullptr, nullptr, biasd);
}

// round 14
// speedup vs baseline: 1.1873x; 1.1873x over previous
#include <cuda_runtime.h>
#include <cuda_bf16.h>
#include <stdint.h>
#include <math.h>

#define NEG_INF (-1e9f)

#define Bsz 32
#define LQ  1024
#define LK  1024
#define DIM 1024
#define HB  (Bsz / 2)   // batches per pipeline half

typedef __nv_bfloat16  bf16;
typedef __nv_bfloat162 bf162;

// ---------------------------------------------------------------------------
// Scratch (__device__ globals; allocation-free rule).
// ---------------------------------------------------------------------------
__device__ bf16 g_combh[(long long)Bsz * LQ * 2 * DIM];  // [32768,2048] mix|q
__device__ bf16 g_combl[(long long)Bsz * LQ * 2 * DIM];
__device__ bf16 g_wh[(long long)Bsz * LQ * LK];          // softmax weights
__device__ bf16 g_wl[(long long)Bsz * LQ * LK];
__device__ bf16 g_qryh[(long long)Bsz * LQ * DIM];
__device__ bf16 g_qryl[(long long)Bsz * LQ * DIM];
__device__ bf16 g_ctxh[(long long)Bsz * LK * DIM];
__device__ bf16 g_ctxl[(long long)Bsz * LK * DIM];
__device__ bf16 g_ctxTh[(long long)Bsz * DIM * LK];
__device__ bf16 g_ctxTl[(long long)Bsz * DIM * LK];
__device__ bf16 g_winh[DIM * DIM];
__device__ bf16 g_winl[DIM * DIM];
__device__ bf16 g_wouth[DIM * 2 * DIM];
__device__ bf16 g_woutl[DIM * 2 * DIM];
__device__ float g_meanf[Bsz * DIM];   // per-batch context mean (fp32)
__device__ bf16  g_mdh[Bsz * DIM];     // mean, split bf16
__device__ bf16  g_mdl[Bsz * DIM];
__device__ float g_biasd[Bsz * DIM];   // mean @ Wout_mix^T (fp32)

// ---------------------------------------------------------------------------
#define SW128(off) ((off) ^ (((off) >> 3) & 0x70))

__device__ __forceinline__ uint32_t smem_u32(const void* p) {
    uint32_t a;
    asm("{ .reg .u64 t; cvta.to.shared.u64 t, %1; cvt.u32.u64 %0, t; }"
        : "=r"(a) : "l"(p));
    return a;
}
__device__ __forceinline__ void cp16(uint32_t dst, const void* src) {
    asm volatile("cp.async.cg.shared.global [%0], [%1], 16;"
                 :: "r"(dst), "l"(src) : "memory");
}
#define CP_COMMIT() asm volatile("cp.async.commit_group;" ::: "memory")
#define CP_WAIT1()  asm volatile("cp.async.wait_group 1;" ::: "memory")

__device__ __forceinline__ void ldsm4(uint32_t* r, uint32_t addr) {
    asm volatile("ldmatrix.sync.aligned.m8n8.x4.shared.b16 {%0,%1,%2,%3}, [%4];"
                 : "=r"(r[0]), "=r"(r[1]), "=r"(r[2]), "=r"(r[3]) : "r"(addr));
}
__device__ __forceinline__ void mma16816(float* c, const uint32_t* a,
                                         uint32_t b0, uint32_t b1) {
    asm volatile(
        "mma.sync.aligned.m16n8k16.row.col.f32.bf16.bf16.f32 "
        "{%0,%1,%2,%3}, {%4,%5,%6,%7}, {%8,%9}, {%0,%1,%2,%3};"
        : "+f"(c[0]), "+f"(c[1]), "+f"(c[2]), "+f"(c[3])
        : "r"(a[0]), "r"(a[1]), "r"(a[2]), "r"(a[3]), "r"(b0), "r"(b1));
}

__device__ __forceinline__ void split2(float a, float b, bf162& hi, bf162& lo) {
    hi = __floats2bfloat162_rn(a, b);
    float2 hf = __bfloat1622float2(hi);
    lo = __floats2bfloat162_rn(a - hf.x, b - hf.y);
}

// ---------------------------------------------------------------------------
// Tile geometry: CTA 256x128, K-chunk 64 bf16 (128B rows, SW128), 512 threads.
// ---------------------------------------------------------------------------
#define TM 256
#define TN 128
#define KC 64
#define NTHR 512
#define OFF_AHI   0
#define OFF_ALO   32768
#define OFF_BHI   65536
#define OFF_BLO   81920
#define STAGE     98304
#define SM_TOTAL  (2 * STAGE)   // 196608

// ---------------------------------------------------------------------------
// split-bf16 mma.sync GEMM: C[m,n] = sum_k A[m,k]*B[n,k]
// EPI:  0 split-bf16 out, 1 length-mask fp32 out, 2 tanh fp32 out
// TRUNC:0 none
//       1 K4: dead tiles (m0>=ql) -> broadcast mean fill; other tiles K-trunc
//             at cl with per-row epilogue mean override for rows >= ql
//       2 K5: dead tiles ((m0&1023)>=ql) -> K restricted to q-half + fp32 bias
// ---------------------------------------------------------------------------
template <int EPI, int TRUNC>
__global__ __launch_bounds__(NTHR, 1)
void mma_gemm(const bf16* __restrict__ Ahi, const bf16* __restrict__ Alo,
              const bf16* __restrict__ Bhi, const bf16* __restrict__ Blo,
              float* __restrict__ Cf, bf16* __restrict__ Chi, bf16* __restrict__ Clo,
              int K, int lda, int ldb, int ldc,
              long long sA, long long sB, long long sC,
              const int* __restrict__ ql, const int* __restrict__ cl,
              const bf16* __restrict__ Dh, const bf16* __restrict__ Dl,
              const float* __restrict__ bias)
{
    extern __shared__ char smem[];
    const uint32_t sb = smem_u32(smem);
    const int tid  = threadIdx.x;
    const int wid  = tid >> 5;
    const int lane = tid & 31;
    const int bz = blockIdx.z;
    const int m0 = blockIdx.y * TM;
    const int n0 = blockIdx.x * TN;

    int qlen = 0, clen = 0;

    // K2 dead tiles: whole tile masked -> fill NEG_INF, no MMA.
    if (EPI == 1) {
        qlen = ql[bz]; clen = cl[bz];
        if (m0 >= qlen || n0 >= clen) {
            const float4 ninf = make_float4(NEG_INF, NEG_INF, NEG_INF, NEG_INF);
            float* base = Cf + (long long)bz * sC;
#pragma unroll 4
            for (int i = tid; i < TM * (TN / 4); i += NTHR) {
                const int r = i / (TN / 4);
                const int c = (i % (TN / 4)) * 4;
                *(float4*)(base + (long long)(m0 + r) * ldc + n0 + c) = ninf;
            }
            return;
        }
    }

    int S = K / KC;

    if (TRUNC == 1) {
        qlen = ql[bz]; clen = cl[bz];
        // dead tile: mix rows are the per-batch context mean -> broadcast fill
        if (m0 >= qlen) {
            for (int i = tid; i < TM * (TN / 2); i += NTHR) {
                const int r  = i / (TN / 2);
                const int c2 = (i % (TN / 2)) * 2;
                bf162 h = *(const bf162*)(Dh + bz * DIM + n0 + c2);
                bf162 l = *(const bf162*)(Dl + bz * DIM + n0 + c2);
                const long long o = (long long)bz * sC + (long long)(m0 + r) * ldc + n0 + c2;
                *(bf162*)(Chi + o) = h;
                *(bf162*)(Clo + o) = l;
            }
            return;
        }
        // live or straddle tile: weights beyond clen are exactly 0 for live
        // rows -> truncate K; dead rows (straddle) fixed up in the epilogue.
        const int se = (clen + KC - 1) / KC;
        if (se < S) S = se;
    }

    bool dead5 = false;
    int batch5 = 0;
    if (TRUNC == 2) {
        batch5 = m0 >> 10;           // TM=256 divides 1024; tile within one batch
        qlen = ql[batch5];
        if ((m0 & (LQ - 1)) >= qlen) { dead5 = true; S = S / 2; }
    }
    const int koff = dead5 ? (K / 2) : 0;   // skip mix half; bias covers it

    Ahi += (long long)bz * sA;  Alo += (long long)bz * sA;
    Bhi += (long long)bz * sB;  Blo += (long long)bz * sB;

    // A fill: 256 rows, 2 threads/row; 32 cols (4 x 16B) of hi and lo
    const int arow = tid >> 1;
    const bf16* Ah = Ahi + (long long)(m0 + arow) * lda + koff + (tid & 1) * 32;
    const bf16* Al = Alo + (long long)(m0 + arow) * lda + koff + (tid & 1) * 32;
    const uint32_t fbA = (uint32_t)(arow * 128 + (tid & 1) * 64);
    // B fill: 128 rows, 4 threads/row; 16 cols (2 x 16B) of hi and lo
    const int brow = tid >> 2;
    const bf16* Bh = Bhi + (long long)(n0 + brow) * ldb + koff + (tid & 3) * 16;
    const bf16* Bl = Blo + (long long)(n0 + brow) * ldb + koff + (tid & 3) * 16;
    const uint32_t fbB = (uint32_t)(brow * 128 + (tid & 3) * 32);

    auto issue = [&](int s) {
        const uint32_t st = sb + (s & 1) * STAGE;
        const int k0 = s * KC;
#pragma unroll
        for (int j = 0; j < 4; j++) {
            const uint32_t sw = SW128(fbA + j * 16);
            cp16(st + OFF_AHI + sw, Ah + k0 + j * 8);
            cp16(st + OFF_ALO + sw, Al + k0 + j * 8);
        }
#pragma unroll
        for (int j = 0; j < 2; j++) {
            const uint32_t sw = SW128(fbB + j * 16);
            cp16(st + OFF_BHI + sw, Bh + k0 + j * 8);
            cp16(st + OFF_BLO + sw, Bl + k0 + j * 8);
        }
        CP_COMMIT();
    };

    issue(0);
    if (S > 1) issue(1); else CP_COMMIT();

    // warp tile: 64x32 (warp grid 4 in M, 4 in N)
    const int wm = (wid & 3) * 64;
    const int wn = (wid >> 2) * 32;
    const int lrow8 = (lane & 7) + ((lane >> 3) & 1) * 8;
    const int lk16  = ((lane >> 4) & 1) * 16;

    float acc[4][4][4];
#pragma unroll
    for (int mt = 0; mt < 4; mt++)
#pragma unroll
        for (int nt = 0; nt < 4; nt++)
#pragma unroll
            for (int i = 0; i < 4; i++) acc[mt][nt][i] = 0.f;

    for (int s = 0; s < S; s++) {
        CP_WAIT1();
        __syncthreads();

        const uint32_t st = sb + (s & 1) * STAGE;
#pragma unroll
        for (int ks = 0; ks < KC / 16; ks++) {
            uint32_t bhi[2][4], blo[2][4];
#pragma unroll
            for (int bt = 0; bt < 2; bt++) {
                uint32_t off = SW128((uint32_t)((wn + bt * 16 + lrow8) * 128 + ks * 32 + lk16));
                ldsm4(bhi[bt], st + OFF_BHI + off);
                ldsm4(blo[bt], st + OFF_BLO + off);
            }
#pragma unroll
            for (int mt = 0; mt < 4; mt++) {
                uint32_t ahi[4], alo[4];
                uint32_t off = SW128((uint32_t)((wm + mt * 16 + lrow8) * 128 + ks * 32 + lk16));
                ldsm4(ahi, st + OFF_AHI + off);
                ldsm4(alo, st + OFF_ALO + off);
#pragma unroll
                for (int nt = 0; nt < 4; nt++)
                    mma16816(acc[mt][nt], ahi, bhi[nt >> 1][nt & 1], bhi[nt >> 1][(nt & 1) + 2]);
#pragma unroll
                for (int nt = 0; nt < 4; nt++)
                    mma16816(acc[mt][nt], ahi, blo[nt >> 1][nt & 1], blo[nt >> 1][(nt & 1) + 2]);
#pragma unroll
                for (int nt = 0; nt < 4; nt++)
                    mma16816(acc[mt][nt], alo, bhi[nt >> 1][nt & 1], bhi[nt >> 1][(nt & 1) + 2]);
            }
        }
        __syncthreads();
        if (s + 2 < S) issue(s + 2);
    }

    // ------------------------- epilogue -------------------------
    const int rq = lane >> 2;
    const int cq = (lane & 3) * 2;

#pragma unroll
    for (int mt = 0; mt < 4; mt++) {
#pragma unroll
        for (int half = 0; half < 2; half++) {
            const int gm = m0 + wm + mt * 16 + rq + half * 8;
            const bool rowdead = (EPI == 1 || TRUNC == 1) && (gm >= qlen);
#pragma unroll
            for (int nt = 0; nt < 4; nt++) {
                const int gn = n0 + wn + nt * 8 + cq;
                float v0 = acc[mt][nt][half * 2 + 0];
                float v1 = acc[mt][nt][half * 2 + 1];
                const long long o = (long long)bz * sC + (long long)gm * ldc + gn;
                if (EPI == 0) {
                    if (TRUNC == 1 && rowdead) {
                        // straddle-tile dead row: mix = per-batch context mean
                        *(bf162*)(Chi + o) = *(const bf162*)(Dh + bz * DIM + gn);
                        *(bf162*)(Clo + o) = *(const bf162*)(Dl + bz * DIM + gn);
                    } else {
                        bf162 hp, lp;
                        split2(v0, v1, hp, lp);
                        *(bf162*)(Chi + o) = hp;
                        *(bf162*)(Clo + o) = lp;
                    }
                } else {
                    if (EPI == 1) {
                        if (rowdead || gn     >= clen) v0 = NEG_INF;
                        if (rowdead || gn + 1 >= clen) v1 = NEG_INF;
                    }
                    if (EPI == 2) {
                        if (TRUNC == 2 && dead5) {
                            v0 += bias[batch5 * DIM + gn];
                            v1 += bias[batch5 * DIM + gn + 1];
                        }
                        v0 = tanhf(v0); v1 = tanhf(v1);
                    }
                    *(float2*)(Cf + o) = make_float2(v0, v1);
                }
            }
        }
    }
}

// ---------------------------------------------------------------------------
// elementwise fp32 -> (hi, lo) bf16 split
// ---------------------------------------------------------------------------
__global__ __launch_bounds__(256)
void convert_split(const float4* __restrict__ src, bf162* __restrict__ hi,
                   bf162* __restrict__ lo, long long n4)
{
    const long long i = (long long)blockIdx.x * blockDim.x + threadIdx.x;
    if (i >= n4) return;
    float4 v = src[i];
    bf162 h0, l0, h1, l1;
    split2(v.x, v.y, h0, l0);
    split2(v.z, v.w, h1, l1);
    hi[2 * i] = h0; hi[2 * i + 1] = h1;
    lo[2 * i] = l0; lo[2 * i + 1] = l1;
}

// ---------------------------------------------------------------------------
// context: split-convert AND transposed split-convert in one pass.
// ---------------------------------------------------------------------------
__global__ __launch_bounds__(256)
void transpose_convert(const float* __restrict__ src,
                       bf16* __restrict__ ch, bf16* __restrict__ cl_,
                       bf16* __restrict__ th, bf16* __restrict__ tl)
{
    __shared__ float t[32][33];
    const long long bo = (long long)blockIdx.z * LK * DIM;
    const int x = blockIdx.x * 32 + threadIdx.x;
    const int y = blockIdx.y * 32 + threadIdx.y;
#pragma unroll
    for (int i = 0; i < 32; i += 8) {
        float v = src[bo + (long long)(y + i) * DIM + x];
        t[threadIdx.y + i][threadIdx.x] = v;
        bf16 h = __float2bfloat16_rn(v);
        bf16 l = __float2bfloat16_rn(v - __bfloat162float(h));
        ch[bo + (long long)(y + i) * DIM + x] = h;
        cl_[bo + (long long)(y + i) * DIM + x] = l;
    }
    __syncthreads();
    const int x2 = blockIdx.y * 32 + threadIdx.x;
    const int y2 = blockIdx.x * 32 + threadIdx.y;
#pragma unroll
    for (int i = 0; i < 32; i += 8) {
        float v = t[threadIdx.x][threadIdx.y + i];
        bf16 h = __float2bfloat16_rn(v);
        bf16 l = __float2bfloat16_rn(v - __bfloat162float(h));
        th[bo + (long long)(y2 + i) * LK + x2] = h;
        tl[bo + (long long)(y2 + i) * LK + x2] = l;
    }
}

// ---------------------------------------------------------------------------
// per-batch context mean over the Lk axis (fp32 + split bf16)
// ---------------------------------------------------------------------------
__global__ __launch_bounds__(256)
void ctx_mean(const float* __restrict__ ctx, float* __restrict__ meanf,
              bf16* __restrict__ mh, bf16* __restrict__ ml)
{
    const int b = blockIdx.y;
    const int d = blockIdx.x * 256 + threadIdx.x;
    const float* p = ctx + (long long)b * LK * DIM + d;
    float s = 0.f;
#pragma unroll 8
    for (int k = 0; k < LK; k++) s += p[(long long)k * DIM];
    s *= (1.0f / (float)LK);
    meanf[b * DIM + d] = s;
    bf16 h = __float2bfloat16_rn(s);
    mh[b * DIM + d] = h;
    ml[b * DIM + d] = __float2bfloat16_rn(s - __bfloat162float(h));
}

// ---------------------------------------------------------------------------
// bias[b][d] = sum_c mean[b][c] * W_out[d][c]  (mix half, fp32, warp-per-output)
// ---------------------------------------------------------------------------
__global__ __launch_bounds__(256)
void bias_gemm(const float* __restrict__ meanf, const float* __restrict__ Wout,
               float* __restrict__ bias)
{
    const int gw = (blockIdx.x * 256 + threadIdx.x) >> 5;   // global warp id
    const int lane = threadIdx.x & 31;
    if (gw >= Bsz * DIM) return;
    const int b = gw >> 10, d = gw & (DIM - 1);
    const float* m = meanf + b * DIM;
    const float* w = Wout + (long long)d * (2 * DIM);
    float s = 0.f;
#pragma unroll 4
    for (int c = lane; c < DIM; c += 32) s += m[c] * w[c];
#pragma unroll
    for (int o = 16; o > 0; o >>= 1) s += __shfl_xor_sync(0xffffffffu, s, o);
    if (lane == 0) bias[gw] = s;
}

// ---------------------------------------------------------------------------
// Row softmax over Lk=1024; emits split bf16 weights.
// Dead rows (r >= ql[b]) are exactly uniform 1/1024 -> constant fill.
// ---------------------------------------------------------------------------
__global__ __launch_bounds__(256)
void softmax_kernel(const float* __restrict__ scores,
                    bf16* __restrict__ wh, bf16* __restrict__ wl,
                    const int* __restrict__ ql)
{
    const long long row = blockIdx.x;
    const int t = threadIdx.x;
    const int b = (int)(row >> 10);
    const int r = (int)(row & (LQ - 1));

    if (r >= ql[b]) {
        const bf162 h = __floats2bfloat162_rn(1.0f / 1024.0f, 1.0f / 1024.0f);
        const bf162 z = __floats2bfloat162_rn(0.0f, 0.0f);
        *(bf162*)(wh + row * LK + 2 * t) = h;
        *(bf162*)(wl + row * LK + 2 * t) = z;
        *(bf162*)(wh + row * LK + 2 * t + 512) = h;
        *(bf162*)(wl + row * LK + 2 * t + 512) = z;
        return;
    }

    const float* s = scores + row * LK;
    float2 x0 = *(const float2*)(s + 2 * t);
    float2 x1 = *(const float2*)(s + 2 * t + 512);
    float lmax = fmaxf(fmaxf(x0.x, x0.y), fmaxf(x1.x, x1.y));

    __shared__ float red[8];
#pragma unroll
    for (int o = 16; o > 0; o >>= 1) lmax = fmaxf(lmax, __shfl_xor_sync(0xffffffffu, lmax, o));
    if ((t & 31) == 0) red[t >> 5] = lmax;
    __syncthreads();
    if (t < 32) {
        float m = (t < 8) ? red[t] : -INFINITY;
#pragma unroll
        for (int o = 4; o > 0; o >>= 1) m = fmaxf(m, __shfl_xor_sync(0xffffffffu, m, o));
        if (t == 0) red[0] = m;
    }
    __syncthreads();
    const float m = red[0];

    float e0 = __expf(x0.x - m), e1 = __expf(x0.y - m);
    float e2 = __expf(x1.x - m), e3 = __expf(x1.y - m);
    float lsum = e0 + e1 + e2 + e3;
#pragma unroll
    for (int o = 16; o > 0; o >>= 1) lsum += __shfl_xor_sync(0xffffffffu, lsum, o);
    __shared__ float red2[8];
    if ((t & 31) == 0) red2[t >> 5] = lsum;
    __syncthreads();
    if (t < 32) {
        float x = (t < 8) ? red2[t] : 0.f;
#pragma unroll
        for (int o = 4; o > 0; o >>= 1) x += __shfl_xor_sync(0xffffffffu, x, o);
        if (t == 0) red2[0] = x;
    }
    __syncthreads();
    const float inv = 1.0f / red2[0];

    bf162 h, l;
    split2(e0 * inv, e1 * inv, h, l);
    *(bf162*)(wh + row * LK + 2 * t) = h;
    *(bf162*)(wl + row * LK + 2 * t) = l;
    split2(e2 * inv, e3 * inv, h, l);
    *(bf162*)(wh + row * LK + 2 * t + 512) = h;
    *(bf162*)(wl + row * LK + 2 * t + 512) = l;
}

// ---------------------------------------------------------------------------
extern "C" void kernel_launch(void* const* d_in, const int* in_sizes, int n_in,
                              void* d_out, int out_size)
{
    const float* query   = (const float*)d_in[0];
    const float* context = (const float*)d_in[1];
    const int*   ql      = (const int*)d_in[2];
    const int*   cl      = (const int*)d_in[3];
    const float* W_in    = (const float*)d_in[4];
    const float* W_out   = (const float*)d_in[5];

    float* out        = (float*)d_out;
    float* scores_out = out + (long long)Bsz * LQ * DIM;

    bf16 *combh, *combl, *wh, *wl, *qryh, *qryl, *ctxh, *ctxl, *ctxTh, *ctxTl;
    bf16 *winh, *winl, *wouth, *woutl, *mdh, *mdl;
    float *meanf, *biasd;
    cudaGetSymbolAddress((void**)&combh, g_combh);
    cudaGetSymbolAddress((void**)&combl, g_combl);
    cudaGetSymbolAddress((void**)&wh,    g_wh);
    cudaGetSymbolAddress((void**)&wl,    g_wl);
    cudaGetSymbolAddress((void**)&qryh,  g_qryh);
    cudaGetSymbolAddress((void**)&qryl,  g_qryl);
    cudaGetSymbolAddress((void**)&ctxh,  g_ctxh);
    cudaGetSymbolAddress((void**)&ctxl,  g_ctxl);
    cudaGetSymbolAddress((void**)&ctxTh, g_ctxTh);
    cudaGetSymbolAddress((void**)&ctxTl, g_ctxTl);
    cudaGetSymbolAddress((void**)&winh,  g_winh);
    cudaGetSymbolAddress((void**)&winl,  g_winl);
    cudaGetSymbolAddress((void**)&wouth, g_wouth);
    cudaGetSymbolAddress((void**)&woutl, g_woutl);
    cudaGetSymbolAddress((void**)&mdh,   g_mdh);
    cudaGetSymbolAddress((void**)&mdl,   g_mdl);
    cudaGetSymbolAddress((void**)&meanf, g_meanf);
    cudaGetSymbolAddress((void**)&biasd, g_biasd);

    cudaFuncSetAttribute(mma_gemm<0, 0>, cudaFuncAttributeMaxDynamicSharedMemorySize, SM_TOTAL);
    cudaFuncSetAttribute(mma_gemm<0, 1>, cudaFuncAttributeMaxDynamicSharedMemorySize, SM_TOTAL);
    cudaFuncSetAttribute(mma_gemm<1, 0>, cudaFuncAttributeMaxDynamicSharedMemorySize, SM_TOTAL);
    cudaFuncSetAttribute(mma_gemm<2, 2>, cudaFuncAttributeMaxDynamicSharedMemorySize, SM_TOTAL);

    // per-half strides (batch offsets)
    const long long QOFF  = (long long)HB * LQ * DIM;      // query/out/q-arrays
    const long long COFF  = (long long)HB * LQ * 2 * DIM;  // comb arrays
    const long long SOFF  = (long long)HB * LQ * LK;       // scores/weights
    const long long XOFF  = (long long)HB * LK * DIM;      // ctx / ctxT
    const long long MOFF  = (long long)HB * DIM;           // mean/bias

    static cudaStream_t s1 = nullptr, s2 = nullptr;
    static cudaEvent_t  ef = nullptr, e1 = nullptr, e2 = nullptr,
                        eqw = nullptr, ek5b = nullptr;
    if (s1 == nullptr) {
        cudaStreamCreateWithFlags(&s1, cudaStreamNonBlocking);
        cudaStreamCreateWithFlags(&s2, cudaStreamNonBlocking);
        cudaEventCreateWithFlags(&ef,   cudaEventDisableTiming);
        cudaEventCreateWithFlags(&e1,   cudaEventDisableTiming);
        cudaEventCreateWithFlags(&e2,   cudaEventDisableTiming);
        cudaEventCreateWithFlags(&eqw,  cudaEventDisableTiming);
        cudaEventCreateWithFlags(&ek5b, cudaEventDisableTiming);
    }

    cudaEventRecord(ef, 0);
    cudaStreamWaitEvent(s1, ef, 0);
    cudaStreamWaitEvent(s2, ef, 0);

    // ---- branch s1: context transforms -> mean -> dead-row bias ----
    transpose_convert<<<dim3(32, 32, Bsz), dim3(32, 8), 0, s1>>>(
        context, ctxh, ctxl, ctxTh, ctxTl);
    ctx_mean<<<dim3(DIM / 256, Bsz), 256, 0, s1>>>(context, meanf, mdh, mdl);
    bias_gemm<<<(Bsz * DIM * 32) / 256, 256, 0, s1>>>(meanf, W_out, biasd);
    cudaEventRecord(e1, s1);

    // ---- main: input conversions (query, W_in) ----
    {
        long long n4 = (long long)Bsz * LQ * DIM / 4;
        convert_split<<<(unsigned)((n4 + 255) / 256), 256>>>(
            (const float4*)query, (bf162*)qryh, (bf162*)qryl, n4);
        long long w4 = (long long)DIM * DIM / 4;
        convert_split<<<(unsigned)((w4 + 255) / 256), 256>>>(
            (const float4*)W_in, (bf162*)winh, (bf162*)winl, w4);
        cudaEventRecord(eqw, 0);
    }

    // ---- branch s2: W_out conversion, then pipeline B (batches 16..31) ----
    {
        long long o4 = (long long)DIM * 2 * DIM / 4;
        convert_split<<<(unsigned)((o4 + 255) / 256), 256, 0, s2>>>(
            (const float4*)W_out, (bf162*)wouth, (bf162*)woutl, o4);
        cudaEventRecord(e2, s2);
    }
    cudaStreamWaitEvent(s2, eqw, 0);

    const unsigned MYH = (unsigned)(HB * LQ / TM);   // 64: M-tiles per half

    // K1b
    mma_gemm<0, 0><<<dim3(DIM / TN, MYH, 1), NTHR, SM_TOTAL, s2>>>(
        qryh + QOFF, qryl + QOFF, winh, winl, nullptr,
        combh + DIM + COFF, combl + DIM + COFF,
        DIM, DIM, DIM, 2 * DIM, 0, 0, 0, nullptr, nullptr,
        nullptr, nullptr, nullptr);
    cudaStreamWaitEvent(s2, e1, 0);
    // K2b
    mma_gemm<1, 0><<<dim3(LK / TN, LQ / TM, HB), NTHR, SM_TOTAL, s2>>>(
        combh + DIM + COFF, combl + DIM + COFF, ctxh + XOFF, ctxl + XOFF,
        scores_out + SOFF, nullptr, nullptr,
        DIM, 2 * DIM, DIM, LK,
        (long long)LQ * 2 * DIM, (long long)LK * DIM, (long long)LQ * LK,
        ql + HB, cl + HB, nullptr, nullptr, nullptr);
    // SMb
    softmax_kernel<<<(unsigned)(HB * LQ), 256, 0, s2>>>(
        scores_out + SOFF, wh + SOFF, wl + SOFF, ql + HB);
    // K4b
    mma_gemm<0, 1><<<dim3(DIM / TN, LQ / TM, HB), NTHR, SM_TOTAL, s2>>>(
        wh + SOFF, wl + SOFF, ctxTh + XOFF, ctxTl + XOFF, nullptr,
        combh + COFF, combl + COFF,
        LK, LK, LK, 2 * DIM,
        (long long)LQ * LK, (long long)DIM * LK, (long long)LQ * 2 * DIM,
        ql + HB, cl + HB, mdh + MOFF, mdl + MOFF, nullptr);
    // K5b (wout ready: same stream as its conversion)
    mma_gemm<2, 2><<<dim3(DIM / TN, MYH, 1), NTHR, SM_TOTAL, s2>>>(
        combh + COFF, combl + COFF, wouth, woutl, out + QOFF, nullptr, nullptr,
        2 * DIM, 2 * DIM, 2 * DIM, DIM, 0, 0, 0, ql + HB, nullptr,
        nullptr, nullptr, biasd + MOFF);
    cudaEventRecord(ek5b, s2);

    // ---- main: pipeline A (batches 0..15) ----
    // K1a
    mma_gemm<0, 0><<<dim3(DIM / TN, MYH, 1), NTHR, SM_TOTAL>>>(
        qryh, qryl, winh, winl, nullptr, combh + DIM, combl + DIM,
        DIM, DIM, DIM, 2 * DIM, 0, 0, 0, nullptr, nullptr,
        nullptr, nullptr, nullptr);
    cudaStreamWaitEvent(0, e1, 0);
    // K2a
    mma_gemm<1, 0><<<dim3(LK / TN, LQ / TM, HB), NTHR, SM_TOTAL>>>(
        combh + DIM, combl + DIM, ctxh, ctxl, scores_out, nullptr, nullptr,
        DIM, 2 * DIM, DIM, LK,
        (long long)LQ * 2 * DIM, (long long)LK * DIM, (long long)LQ * LK,
        ql, cl, nullptr, nullptr, nullptr);
    // SMa
    softmax_kernel<<<(unsigned)(HB * LQ), 256>>>(scores_out, wh, wl, ql);
    // K4a
    mma_gemm<0, 1><<<dim3(DIM / TN, LQ / TM, HB), NTHR, SM_TOTAL>>>(
        wh, wl, ctxTh, ctxTl, nullptr, combh, combl,
        LK, LK, LK, 2 * DIM,
        (long long)LQ * LK, (long long)DIM * LK, (long long)LQ * 2 * DIM,
        ql, cl, mdh, mdl, nullptr);
    // K5a (needs W_out conversion from s2)
    cudaStreamWaitEvent(0, e2, 0);
    mma_gemm<2, 2><<<dim3(DIM / TN, MYH, 1), NTHR, SM_TOTAL>>>(
        combh, combl, wouth, woutl, out, nullptr, nullptr,
        2 * DIM, 2 * DIM, 2 * DIM, DIM, 0, 0, 0, ql, nullptr,
        nullptr, nullptr, biasd);

    // join pipeline B before returning
    cudaStreamWaitEvent(0, ek5b, 0);
}

// round 16
// speedup vs baseline: 1.1918x; 1.0038x over previous
#include <cuda_runtime.h>
#include <cuda_bf16.h>
#include <stdint.h>
#include <math.h>

#define NEG_INF (-1e9f)

#define Bsz 32
#define LQ  1024
#define LK  1024
#define DIM 1024
#define HB  (Bsz / 2)   // batches per pipeline half

typedef __nv_bfloat16  bf16;
typedef __nv_bfloat162 bf162;

// ---------------------------------------------------------------------------
// Scratch (__device__ globals; allocation-free rule).
// ---------------------------------------------------------------------------
__device__ bf16 g_combh[(long long)Bsz * LQ * 2 * DIM];  // [32768,2048] mix|q
__device__ bf16 g_combl[(long long)Bsz * LQ * 2 * DIM];
__device__ bf16 g_wh[(long long)Bsz * LQ * LK];          // softmax weights
__device__ bf16 g_wl[(long long)Bsz * LQ * LK];
__device__ bf16 g_qryh[(long long)Bsz * LQ * DIM];
__device__ bf16 g_qryl[(long long)Bsz * LQ * DIM];
__device__ bf16 g_ctxh[(long long)Bsz * LK * DIM];
__device__ bf16 g_ctxl[(long long)Bsz * LK * DIM];
__device__ bf16 g_ctxTh[(long long)Bsz * DIM * LK];
__device__ bf16 g_ctxTl[(long long)Bsz * DIM * LK];
__device__ bf16 g_winh[DIM * DIM];
__device__ bf16 g_winl[DIM * DIM];
__device__ bf16 g_wouth[DIM * 2 * DIM];
__device__ bf16 g_woutl[DIM * 2 * DIM];
__device__ float g_meanf[Bsz * DIM];   // per-batch context mean (fp32)
__device__ bf16  g_mdh[Bsz * DIM];     // mean, split bf16
__device__ bf16  g_mdl[Bsz * DIM];
__device__ float g_biasd[Bsz * DIM];   // mean @ Wout_mix^T (fp32)

// ---------------------------------------------------------------------------
#define SW128(off) ((off) ^ (((off) >> 3) & 0x70))

__device__ __forceinline__ uint32_t smem_u32(const void* p) {
    uint32_t a;
    asm("{ .reg .u64 t; cvta.to.shared.u64 t, %1; cvt.u32.u64 %0, t; }"
        : "=r"(a) : "l"(p));
    return a;
}
__device__ __forceinline__ void cp16(uint32_t dst, const void* src) {
    asm volatile("cp.async.cg.shared.global [%0], [%1], 16;"
                 :: "r"(dst), "l"(src) : "memory");
}
#define CP_COMMIT() asm volatile("cp.async.commit_group;" ::: "memory")
#define CP_WAIT1()  asm volatile("cp.async.wait_group 1;" ::: "memory")

__device__ __forceinline__ void ldsm4(uint32_t* r, uint32_t addr) {
    asm volatile("ldmatrix.sync.aligned.m8n8.x4.shared.b16 {%0,%1,%2,%3}, [%4];"
                 : "=r"(r[0]), "=r"(r[1]), "=r"(r[2]), "=r"(r[3]) : "r"(addr));
}
__device__ __forceinline__ void mma16816(float* c, const uint32_t* a,
                                         uint32_t b0, uint32_t b1) {
    asm volatile(
        "mma.sync.aligned.m16n8k16.row.col.f32.bf16.bf16.f32 "
        "{%0,%1,%2,%3}, {%4,%5,%6,%7}, {%8,%9}, {%0,%1,%2,%3};"
        : "+f"(c[0]), "+f"(c[1]), "+f"(c[2]), "+f"(c[3])
        : "r"(a[0]), "r"(a[1]), "r"(a[2]), "r"(a[3]), "r"(b0), "r"(b1));
}

__device__ __forceinline__ void split2(float a, float b, bf162& hi, bf162& lo) {
    hi = __floats2bfloat162_rn(a, b);
    float2 hf = __bfloat1622float2(hi);
    lo = __floats2bfloat162_rn(a - hf.x, b - hf.y);
}

// ---------------------------------------------------------------------------
// Tile geometry: CTA 256x128, K-chunk 64 bf16 (128B rows, SW128), 512 threads.
// ---------------------------------------------------------------------------
#define TM 256
#define TN 128
#define KC 64
#define NTHR 512
#define OFF_AHI   0
#define OFF_ALO   32768
#define OFF_BHI   65536
#define OFF_BLO   81920
#define STAGE     98304
#define SM_TOTAL  (2 * STAGE)   // 196608

// ---------------------------------------------------------------------------
// split-bf16 mma.sync GEMM: C[m,n] = sum_k A[m,k]*B[n,k]
// EPI:  0 split-bf16 out, 1 length-mask fp32 out, 2 tanh fp32 out
// TRUNC:0 none
//       1 K4: dead tiles (m0>=ql) -> broadcast mean fill; other tiles K-trunc
//             at cl with per-row epilogue mean override for rows >= ql
//       2 K5: dead tiles ((m0&1023)>=ql) -> K restricted to q-half + fp32 bias
// ---------------------------------------------------------------------------
template <int EPI, int TRUNC>
__global__ __launch_bounds__(NTHR, 1)
void mma_gemm(const bf16* __restrict__ Ahi, const bf16* __restrict__ Alo,
              const bf16* __restrict__ Bhi, const bf16* __restrict__ Blo,
              float* __restrict__ Cf, bf16* __restrict__ Chi, bf16* __restrict__ Clo,
              int K, int lda, int ldb, int ldc,
              long long sA, long long sB, long long sC,
              const int* __restrict__ ql, const int* __restrict__ cl,
              const bf16* __restrict__ Dh, const bf16* __restrict__ Dl,
              const float* __restrict__ bias)
{
    extern __shared__ char smem[];
    const uint32_t sb = smem_u32(smem);
    const int tid  = threadIdx.x;
    const int wid  = tid >> 5;
    const int lane = tid & 31;
    const int bz = blockIdx.z;
    const int m0 = blockIdx.y * TM;
    const int n0 = blockIdx.x * TN;

    int qlen = 0, clen = 0;

    // K2 dead tiles: whole tile masked -> fill NEG_INF, no MMA.
    if (EPI == 1) {
        qlen = ql[bz]; clen = cl[bz];
        if (m0 >= qlen || n0 >= clen) {
            const float4 ninf = make_float4(NEG_INF, NEG_INF, NEG_INF, NEG_INF);
            float* base = Cf + (long long)bz * sC;
#pragma unroll 4
            for (int i = tid; i < TM * (TN / 4); i += NTHR) {
                const int r = i / (TN / 4);
                const int c = (i % (TN / 4)) * 4;
                *(float4*)(base + (long long)(m0 + r) * ldc + n0 + c) = ninf;
            }
            return;
        }
    }

    int S = K / KC;

    if (TRUNC == 1) {
        qlen = ql[bz]; clen = cl[bz];
        // dead tile: mix rows are the per-batch context mean -> broadcast fill
        if (m0 >= qlen) {
            for (int i = tid; i < TM * (TN / 2); i += NTHR) {
                const int r  = i / (TN / 2);
                const int c2 = (i % (TN / 2)) * 2;
                bf162 h = *(const bf162*)(Dh + bz * DIM + n0 + c2);
                bf162 l = *(const bf162*)(Dl + bz * DIM + n0 + c2);
                const long long o = (long long)bz * sC + (long long)(m0 + r) * ldc + n0 + c2;
                *(bf162*)(Chi + o) = h;
                *(bf162*)(Clo + o) = l;
            }
            return;
        }
        // live or straddle tile: weights beyond clen are exactly 0 for live
        // rows -> truncate K; dead rows (straddle) fixed up in the epilogue.
        const int se = (clen + KC - 1) / KC;
        if (se < S) S = se;
    }

    bool dead5 = false;
    int batch5 = 0;
    if (TRUNC == 2) {
        batch5 = m0 >> 10;           // TM=256 divides 1024; tile within one batch
        qlen = ql[batch5];
        if ((m0 & (LQ - 1)) >= qlen) { dead5 = true; S = S / 2; }
    }
    const int koff = dead5 ? (K / 2) : 0;   // skip mix half; bias covers it

    Ahi += (long long)bz * sA;  Alo += (long long)bz * sA;
    Bhi += (long long)bz * sB;  Blo += (long long)bz * sB;

    // A fill: 256 rows, 2 threads/row; 32 cols (4 x 16B) of hi and lo
    const int arow = tid >> 1;
    const bf16* Ah = Ahi + (long long)(m0 + arow) * lda + koff + (tid & 1) * 32;
    const bf16* Al = Alo + (long long)(m0 + arow) * lda + koff + (tid & 1) * 32;
    const uint32_t fbA = (uint32_t)(arow * 128 + (tid & 1) * 64);
    // B fill: 128 rows, 4 threads/row; 16 cols (2 x 16B) of hi and lo
    const int brow = tid >> 2;
    const bf16* Bh = Bhi + (long long)(n0 + brow) * ldb + koff + (tid & 3) * 16;
    const bf16* Bl = Blo + (long long)(n0 + brow) * ldb + koff + (tid & 3) * 16;
    const uint32_t fbB = (uint32_t)(brow * 128 + (tid & 3) * 32);

    auto issue = [&](int s) {
        const uint32_t st = sb + (s & 1) * STAGE;
        const int k0 = s * KC;
#pragma unroll
        for (int j = 0; j < 4; j++) {
            const uint32_t sw = SW128(fbA + j * 16);
            cp16(st + OFF_AHI + sw, Ah + k0 + j * 8);
            cp16(st + OFF_ALO + sw, Al + k0 + j * 8);
        }
#pragma unroll
        for (int j = 0; j < 2; j++) {
            const uint32_t sw = SW128(fbB + j * 16);
            cp16(st + OFF_BHI + sw, Bh + k0 + j * 8);
            cp16(st + OFF_BLO + sw, Bl + k0 + j * 8);
        }
        CP_COMMIT();
    };

    issue(0);
    if (S > 1) issue(1); else CP_COMMIT();

    // warp tile: 64x32 (warp grid 4 in M, 4 in N)
    const int wm = (wid & 3) * 64;
    const int wn = (wid >> 2) * 32;
    const int lrow8 = (lane & 7) + ((lane >> 3) & 1) * 8;
    const int lk16  = ((lane >> 4) & 1) * 16;

    float acc[4][4][4];
#pragma unroll
    for (int mt = 0; mt < 4; mt++)
#pragma unroll
        for (int nt = 0; nt < 4; nt++)
#pragma unroll
            for (int i = 0; i < 4; i++) acc[mt][nt][i] = 0.f;

    for (int s = 0; s < S; s++) {
        CP_WAIT1();
        __syncthreads();

        const uint32_t st = sb + (s & 1) * STAGE;
#pragma unroll
        for (int ks = 0; ks < KC / 16; ks++) {
            uint32_t bhi[2][4], blo[2][4];
#pragma unroll
            for (int bt = 0; bt < 2; bt++) {
                uint32_t off = SW128((uint32_t)((wn + bt * 16 + lrow8) * 128 + ks * 32 + lk16));
                ldsm4(bhi[bt], st + OFF_BHI + off);
                ldsm4(blo[bt], st + OFF_BLO + off);
            }
#pragma unroll
            for (int mt = 0; mt < 4; mt++) {
                uint32_t ahi[4], alo[4];
                uint32_t off = SW128((uint32_t)((wm + mt * 16 + lrow8) * 128 + ks * 32 + lk16));
                ldsm4(ahi, st + OFF_AHI + off);
                ldsm4(alo, st + OFF_ALO + off);
#pragma unroll
                for (int nt = 0; nt < 4; nt++)
                    mma16816(acc[mt][nt], ahi, bhi[nt >> 1][nt & 1], bhi[nt >> 1][(nt & 1) + 2]);
#pragma unroll
                for (int nt = 0; nt < 4; nt++)
                    mma16816(acc[mt][nt], ahi, blo[nt >> 1][nt & 1], blo[nt >> 1][(nt & 1) + 2]);
#pragma unroll
                for (int nt = 0; nt < 4; nt++)
                    mma16816(acc[mt][nt], alo, bhi[nt >> 1][nt & 1], bhi[nt >> 1][(nt & 1) + 2]);
            }
        }
        __syncthreads();
        if (s + 2 < S) issue(s + 2);
    }

    // ------------------------- epilogue -------------------------
    const int rq = lane >> 2;
    const int cq = (lane & 3) * 2;

#pragma unroll
    for (int mt = 0; mt < 4; mt++) {
#pragma unroll
        for (int half = 0; half < 2; half++) {
            const int gm = m0 + wm + mt * 16 + rq + half * 8;
            const bool rowdead = (EPI == 1 || TRUNC == 1) && (gm >= qlen);
#pragma unroll
            for (int nt = 0; nt < 4; nt++) {
                const int gn = n0 + wn + nt * 8 + cq;
                float v0 = acc[mt][nt][half * 2 + 0];
                float v1 = acc[mt][nt][half * 2 + 1];
                const long long o = (long long)bz * sC + (long long)gm * ldc + gn;
                if (EPI == 0) {
                    if (TRUNC == 1 && rowdead) {
                        // straddle-tile dead row: mix = per-batch context mean
                        *(bf162*)(Chi + o) = *(const bf162*)(Dh + bz * DIM + gn);
                        *(bf162*)(Clo + o) = *(const bf162*)(Dl + bz * DIM + gn);
                    } else {
                        bf162 hp, lp;
                        split2(v0, v1, hp, lp);
                        *(bf162*)(Chi + o) = hp;
                        *(bf162*)(Clo + o) = lp;
                    }
                } else {
                    if (EPI == 1) {
                        if (rowdead || gn     >= clen) v0 = NEG_INF;
                        if (rowdead || gn + 1 >= clen) v1 = NEG_INF;
                    }
                    if (EPI == 2) {
                        if (TRUNC == 2 && dead5) {
                            v0 += bias[batch5 * DIM + gn];
                            v1 += bias[batch5 * DIM + gn + 1];
                        }
                        v0 = tanhf(v0); v1 = tanhf(v1);
                    }
                    *(float2*)(Cf + o) = make_float2(v0, v1);
                }
            }
        }
    }
}

// ---------------------------------------------------------------------------
// elementwise fp32 -> (hi, lo) bf16 split
// ---------------------------------------------------------------------------
__global__ __launch_bounds__(256)
void convert_split(const float4* __restrict__ src, bf162* __restrict__ hi,
                   bf162* __restrict__ lo, long long n4)
{
    const long long i = (long long)blockIdx.x * blockDim.x + threadIdx.x;
    if (i >= n4) return;
    float4 v = src[i];
    bf162 h0, l0, h1, l1;
    split2(v.x, v.y, h0, l0);
    split2(v.z, v.w, h1, l1);
    hi[2 * i] = h0; hi[2 * i + 1] = h1;
    lo[2 * i] = l0; lo[2 * i + 1] = l1;
}

// ---------------------------------------------------------------------------
// context: split-convert AND transposed split-convert in one pass.
// ---------------------------------------------------------------------------
__global__ __launch_bounds__(256)
void transpose_convert(const float* __restrict__ src,
                       bf16* __restrict__ ch, bf16* __restrict__ cl_,
                       bf16* __restrict__ th, bf16* __restrict__ tl)
{
    __shared__ float t[32][33];
    const long long bo = (long long)blockIdx.z * LK * DIM;
    const int x = blockIdx.x * 32 + threadIdx.x;
    const int y = blockIdx.y * 32 + threadIdx.y;
#pragma unroll
    for (int i = 0; i < 32; i += 8) {
        float v = src[bo + (long long)(y + i) * DIM + x];
        t[threadIdx.y + i][threadIdx.x] = v;
        bf16 h = __float2bfloat16_rn(v);
        bf16 l = __float2bfloat16_rn(v - __bfloat162float(h));
        ch[bo + (long long)(y + i) * DIM + x] = h;
        cl_[bo + (long long)(y + i) * DIM + x] = l;
    }
    __syncthreads();
    const int x2 = blockIdx.y * 32 + threadIdx.x;
    const int y2 = blockIdx.x * 32 + threadIdx.y;
#pragma unroll
    for (int i = 0; i < 32; i += 8) {
        float v = t[threadIdx.x][threadIdx.y + i];
        bf16 h = __float2bfloat16_rn(v);
        bf16 l = __float2bfloat16_rn(v - __bfloat162float(h));
        th[bo + (long long)(y2 + i) * LK + x2] = h;
        tl[bo + (long long)(y2 + i) * LK + x2] = l;
    }
}

// ---------------------------------------------------------------------------
// per-batch context mean over the Lk axis (fp32 + split bf16)
// ---------------------------------------------------------------------------
__global__ __launch_bounds__(256)
void ctx_mean(const float* __restrict__ ctx, float* __restrict__ meanf,
              bf16* __restrict__ mh, bf16* __restrict__ ml)
{
    const int b = blockIdx.y;
    const int d = blockIdx.x * 256 + threadIdx.x;
    const float* p = ctx + (long long)b * LK * DIM + d;
    float s = 0.f;
#pragma unroll 8
    for (int k = 0; k < LK; k++) s += p[(long long)k * DIM];
    s *= (1.0f / (float)LK);
    meanf[b * DIM + d] = s;
    bf16 h = __float2bfloat16_rn(s);
    mh[b * DIM + d] = h;
    ml[b * DIM + d] = __float2bfloat16_rn(s - __bfloat162float(h));
}

// ---------------------------------------------------------------------------
// bias[b][d] = sum_c mean[b][c] * W_out[d][c]  (mix half, fp32, warp-per-output)
// ---------------------------------------------------------------------------
__global__ __launch_bounds__(256)
void bias_gemm(const float* __restrict__ meanf, const float* __restrict__ Wout,
               float* __restrict__ bias)
{
    const int gw = (blockIdx.x * 256 + threadIdx.x) >> 5;   // global warp id
    const int lane = threadIdx.x & 31;
    if (gw >= Bsz * DIM) return;
    const int b = gw >> 10, d = gw & (DIM - 1);
    const float* m = meanf + b * DIM;
    const float* w = Wout + (long long)d * (2 * DIM);
    float s = 0.f;
#pragma unroll 4
    for (int c = lane; c < DIM; c += 32) s += m[c] * w[c];
#pragma unroll
    for (int o = 16; o > 0; o >>= 1) s += __shfl_xor_sync(0xffffffffu, s, o);
    if (lane == 0) bias[gw] = s;
}

// ---------------------------------------------------------------------------
// Row softmax over Lk=1024; emits split bf16 weights.
// Dead rows (r >= ql[b]) are exactly uniform 1/1024 -> constant fill.
// ---------------------------------------------------------------------------
__global__ __launch_bounds__(256)
void softmax_kernel(const float* __restrict__ scores,
                    bf16* __restrict__ wh, bf16* __restrict__ wl,
                    const int* __restrict__ ql)
{
    const long long row = blockIdx.x;
    const int t = threadIdx.x;
    const int b = (int)(row >> 10);
    const int r = (int)(row & (LQ - 1));

    if (r >= ql[b]) {
        const bf162 h = __floats2bfloat162_rn(1.0f / 1024.0f, 1.0f / 1024.0f);
        const bf162 z = __floats2bfloat162_rn(0.0f, 0.0f);
        *(bf162*)(wh + row * LK + 2 * t) = h;
        *(bf162*)(wl + row * LK + 2 * t) = z;
        *(bf162*)(wh + row * LK + 2 * t + 512) = h;
        *(bf162*)(wl + row * LK + 2 * t + 512) = z;
        return;
    }

    const float* s = scores + row * LK;
    float2 x0 = *(const float2*)(s + 2 * t);
    float2 x1 = *(const float2*)(s + 2 * t + 512);
    float lmax = fmaxf(fmaxf(x0.x, x0.y), fmaxf(x1.x, x1.y));

    __shared__ float red[8];
#pragma unroll
    for (int o = 16; o > 0; o >>= 1) lmax = fmaxf(lmax, __shfl_xor_sync(0xffffffffu, lmax, o));
    if ((t & 31) == 0) red[t >> 5] = lmax;
    __syncthreads();
    if (t < 32) {
        float m = (t < 8) ? red[t] : -INFINITY;
#pragma unroll
        for (int o = 4; o > 0; o >>= 1) m = fmaxf(m, __shfl_xor_sync(0xffffffffu, m, o));
        if (t == 0) red[0] = m;
    }
    __syncthreads();
    const float m = red[0];

    float e0 = __expf(x0.x - m), e1 = __expf(x0.y - m);
    float e2 = __expf(x1.x - m), e3 = __expf(x1.y - m);
    float lsum = e0 + e1 + e2 + e3;
#pragma unroll
    for (int o = 16; o > 0; o >>= 1) lsum += __shfl_xor_sync(0xffffffffu, lsum, o);
    __shared__ float red2[8];
    if ((t & 31) == 0) red2[t >> 5] = lsum;
    __syncthreads();
    if (t < 32) {
        float x = (t < 8) ? red2[t] : 0.f;
#pragma unroll
        for (int o = 4; o > 0; o >>= 1) x += __shfl_xor_sync(0xffffffffu, x, o);
        if (t == 0) red2[0] = x;
    }
    __syncthreads();
    const float inv = 1.0f / red2[0];

    bf162 h, l;
    split2(e0 * inv, e1 * inv, h, l);
    *(bf162*)(wh + row * LK + 2 * t) = h;
    *(bf162*)(wl + row * LK + 2 * t) = l;
    split2(e2 * inv, e3 * inv, h, l);
    *(bf162*)(wh + row * LK + 2 * t + 512) = h;
    *(bf162*)(wl + row * LK + 2 * t + 512) = l;
}

// ---------------------------------------------------------------------------
extern "C" void kernel_launch(void* const* d_in, const int* in_sizes, int n_in,
                              void* d_out, int out_size)
{
    const float* query   = (const float*)d_in[0];
    const float* context = (const float*)d_in[1];
    const int*   ql      = (const int*)d_in[2];
    const int*   cl      = (const int*)d_in[3];
    const float* W_in    = (const float*)d_in[4];
    const float* W_out   = (const float*)d_in[5];

    float* out        = (float*)d_out;
    float* scores_out = out + (long long)Bsz * LQ * DIM;

    bf16 *combh, *combl, *wh, *wl, *qryh, *qryl, *ctxh, *ctxl, *ctxTh, *ctxTl;
    bf16 *winh, *winl, *wouth, *woutl, *mdh, *mdl;
    float *meanf, *biasd;
    cudaGetSymbolAddress((void**)&combh, g_combh);
    cudaGetSymbolAddress((void**)&combl, g_combl);
    cudaGetSymbolAddress((void**)&wh,    g_wh);
    cudaGetSymbolAddress((void**)&wl,    g_wl);
    cudaGetSymbolAddress((void**)&qryh,  g_qryh);
    cudaGetSymbolAddress((void**)&qryl,  g_qryl);
    cudaGetSymbolAddress((void**)&ctxh,  g_ctxh);
    cudaGetSymbolAddress((void**)&ctxl,  g_ctxl);
    cudaGetSymbolAddress((void**)&ctxTh, g_ctxTh);
    cudaGetSymbolAddress((void**)&ctxTl, g_ctxTl);
    cudaGetSymbolAddress((void**)&winh,  g_winh);
    cudaGetSymbolAddress((void**)&winl,  g_winl);
    cudaGetSymbolAddress((void**)&wouth, g_wouth);
    cudaGetSymbolAddress((void**)&woutl, g_woutl);
    cudaGetSymbolAddress((void**)&mdh,   g_mdh);
    cudaGetSymbolAddress((void**)&mdl,   g_mdl);
    cudaGetSymbolAddress((void**)&meanf, g_meanf);
    cudaGetSymbolAddress((void**)&biasd, g_biasd);

    cudaFuncSetAttribute(mma_gemm<0, 0>, cudaFuncAttributeMaxDynamicSharedMemorySize, SM_TOTAL);
    cudaFuncSetAttribute(mma_gemm<0, 1>, cudaFuncAttributeMaxDynamicSharedMemorySize, SM_TOTAL);
    cudaFuncSetAttribute(mma_gemm<1, 0>, cudaFuncAttributeMaxDynamicSharedMemorySize, SM_TOTAL);
    cudaFuncSetAttribute(mma_gemm<2, 2>, cudaFuncAttributeMaxDynamicSharedMemorySize, SM_TOTAL);

    // per-half strides (batch offsets)
    const long long QOFF  = (long long)HB * LQ * DIM;      // query/out/q-arrays
    const long long COFF  = (long long)HB * LQ * 2 * DIM;  // comb arrays
    const long long SOFF  = (long long)HB * LQ * LK;       // scores/weights
    const long long XOFF  = (long long)HB * LK * DIM;      // ctx / ctxT
    const long long MOFF  = (long long)HB * DIM;           // mean/bias

    static cudaStream_t s1 = nullptr, s2 = nullptr;
    static cudaEvent_t  ef = nullptr, e1 = nullptr, e2 = nullptr,
                        eqw = nullptr, ek5b = nullptr;
    if (s1 == nullptr) {
        cudaStreamCreateWithFlags(&s1, cudaStreamNonBlocking);
        cudaStreamCreateWithFlags(&s2, cudaStreamNonBlocking);
        cudaEventCreateWithFlags(&ef,   cudaEventDisableTiming);
        cudaEventCreateWithFlags(&e1,   cudaEventDisableTiming);
        cudaEventCreateWithFlags(&e2,   cudaEventDisableTiming);
        cudaEventCreateWithFlags(&eqw,  cudaEventDisableTiming);
        cudaEventCreateWithFlags(&ek5b, cudaEventDisableTiming);
    }

    cudaEventRecord(ef, 0);
    cudaStreamWaitEvent(s1, ef, 0);
    cudaStreamWaitEvent(s2, ef, 0);

    // ---- branch s1: context transforms -> mean -> dead-row bias ----
    transpose_convert<<<dim3(32, 32, Bsz), dim3(32, 8), 0, s1>>>(
        context, ctxh, ctxl, ctxTh, ctxTl);
    ctx_mean<<<dim3(DIM / 256, Bsz), 256, 0, s1>>>(context, meanf, mdh, mdl);
    bias_gemm<<<(Bsz * DIM * 32) / 256, 256, 0, s1>>>(meanf, W_out, biasd);
    cudaEventRecord(e1, s1);

    const long long h4 = (long long)HB * LQ * DIM / 4;   // fp32 float4s per half

    // ---- main: W_in conversion (shared) + query half A conversion ----
    {
        long long w4 = (long long)DIM * DIM / 4;
        convert_split<<<(unsigned)((w4 + 255) / 256), 256>>>(
            (const float4*)W_in, (bf162*)winh, (bf162*)winl, w4);
        cudaEventRecord(eqw, 0);   // W_in ready
        convert_split<<<(unsigned)((h4 + 255) / 256), 256>>>(
            (const float4*)query, (bf162*)qryh, (bf162*)qryl, h4);
    }

    // ---- branch s2: W_out conversion + query half B, then pipeline B ----
    {
        long long o4 = (long long)DIM * 2 * DIM / 4;
        convert_split<<<(unsigned)((o4 + 255) / 256), 256, 0, s2>>>(
            (const float4*)W_out, (bf162*)wouth, (bf162*)woutl, o4);
        cudaEventRecord(e2, s2);
        convert_split<<<(unsigned)((h4 + 255) / 256), 256, 0, s2>>>(
            (const float4*)(query + QOFF), (bf162*)(qryh + QOFF),
            (bf162*)(qryl + QOFF), h4);
    }
    cudaStreamWaitEvent(s2, eqw, 0);   // W_in ready for K1b

    const unsigned MYH = (unsigned)(HB * LQ / TM);   // 64: M-tiles per half

    // K1b
    mma_gemm<0, 0><<<dim3(DIM / TN, MYH, 1), NTHR, SM_TOTAL, s2>>>(
        qryh + QOFF, qryl + QOFF, winh, winl, nullptr,
        combh + DIM + COFF, combl + DIM + COFF,
        DIM, DIM, DIM, 2 * DIM, 0, 0, 0, nullptr, nullptr,
        nullptr, nullptr, nullptr);
    cudaStreamWaitEvent(s2, e1, 0);
    // K2b
    mma_gemm<1, 0><<<dim3(LK / TN, LQ / TM, HB), NTHR, SM_TOTAL, s2>>>(
        combh + DIM + COFF, combl + DIM + COFF, ctxh + XOFF, ctxl + XOFF,
        scores_out + SOFF, nullptr, nullptr,
        DIM, 2 * DIM, DIM, LK,
        (long long)LQ * 2 * DIM, (long long)LK * DIM, (long long)LQ * LK,
        ql + HB, cl + HB, nullptr, nullptr, nullptr);
    // SMb
    softmax_kernel<<<(unsigned)(HB * LQ), 256, 0, s2>>>(
        scores_out + SOFF, wh + SOFF, wl + SOFF, ql + HB);
    // K4b
    mma_gemm<0, 1><<<dim3(DIM / TN, LQ / TM, HB), NTHR, SM_TOTAL, s2>>>(
        wh + SOFF, wl + SOFF, ctxTh + XOFF, ctxTl + XOFF, nullptr,
        combh + COFF, combl + COFF,
        LK, LK, LK, 2 * DIM,
        (long long)LQ * LK, (long long)DIM * LK, (long long)LQ * 2 * DIM,
        ql + HB, cl + HB, mdh + MOFF, mdl + MOFF, nullptr);
    // K5b (wout ready: same stream as its conversion)
    mma_gemm<2, 2><<<dim3(DIM / TN, MYH, 1), NTHR, SM_TOTAL, s2>>>(
        combh + COFF, combl + COFF, wouth, woutl, out + QOFF, nullptr, nullptr,
        2 * DIM, 2 * DIM, 2 * DIM, DIM, 0, 0, 0, ql + HB, nullptr,
        nullptr, nullptr, biasd + MOFF);
    cudaEventRecord(ek5b, s2);

    // ---- main: pipeline A (batches 0..15) ----
    // K1a
    mma_gemm<0, 0><<<dim3(DIM / TN, MYH, 1), NTHR, SM_TOTAL>>>(
        qryh, qryl, winh, winl, nullptr, combh + DIM, combl + DIM,
        DIM, DIM, DIM, 2 * DIM, 0, 0, 0, nullptr, nullptr,
        nullptr, nullptr, nullptr);
    cudaStreamWaitEvent(0, e1, 0);
    // K2a
    mma_gemm<1, 0><<<dim3(LK / TN, LQ / TM, HB), NTHR, SM_TOTAL>>>(
        combh + DIM, combl + DIM, ctxh, ctxl, scores_out, nullptr, nullptr,
        DIM, 2 * DIM, DIM, LK,
        (long long)LQ * 2 * DIM, (long long)LK * DIM, (long long)LQ * LK,
        ql, cl, nullptr, nullptr, nullptr);
    // SMa
    softmax_kernel<<<(unsigned)(HB * LQ), 256>>>(scores_out, wh, wl, ql);
    // K4a
    mma_gemm<0, 1><<<dim3(DIM / TN, LQ / TM, HB), NTHR, SM_TOTAL>>>(
        wh, wl, ctxTh, ctxTl, nullptr, combh, combl,
        LK, LK, LK, 2 * DIM,
        (long long)LQ * LK, (long long)DIM * LK, (long long)LQ * 2 * DIM,
        ql, cl, mdh, mdl, nullptr);
    // K5a (needs W_out conversion from s2)
    cudaStreamWaitEvent(0, e2, 0);
    mma_gemm<2, 2><<<dim3(DIM / TN, MYH, 1), NTHR, SM_TOTAL>>>(
        combh, combl, wouth, woutl, out, nullptr, nullptr,
        2 * DIM, 2 * DIM, 2 * DIM, DIM, 0, 0, 0, ql, nullptr,
        nullptr, nullptr, biasd);

    // join pipeline B before returning
    cudaStreamWaitEvent(0, ek5b, 0);
}